// round 15
// baseline (speedup 1.0000x reference)
#include <cuda_runtime.h>
#include <cuda_fp16.h>
#include <cstdint>

// Problem constants
#define NB 2
#define NS 2048
#define ND 1024
#define NH 16
#define NDH 64
#define NM (NB * NS)

// Scratch (device globals: allocation-free)
__device__ __half g_xh[3][(size_t)NM * ND];            // fp16 copies of Xq,Xk,Xv
__device__ __half g_wh[4][(size_t)ND * ND];            // fp16 copies of Wq,Wk,Wv,Wo
__device__ __half g_q[(size_t)NB * NH * NS * NDH];     // [b,h,s,dh]
__device__ __half g_k[(size_t)NB * NH * NS * NDH];     // [b,h,s,dh]
__device__ __half g_v[(size_t)NB * NH * NS * NDH];     // [b,h,dh,s]  TRANSPOSED
__device__ __half g_attn[(size_t)NB * NS * ND];        // fp16 concat output
__device__ __half g_ew[(size_t)NB * NH * NS * NS];     // fp16 unnormalized weights
__device__ float  g_rowsum[(size_t)NB * NH * NS];
__device__ uint32_t g_pm[(size_t)NB * NS * (NS / 32)]; // bit-packed mask

// ---------------- helpers ----------------
__device__ __forceinline__ uint32_t f2h2(float a, float b) {
    __half2 h = __floats2half2_rn(a, b);
    return *reinterpret_cast<uint32_t*>(&h);
}

__device__ __forceinline__ void mma_f16(float c[4], const uint32_t a[4], const uint32_t b[2]) {
    asm volatile(
        "mma.sync.aligned.m16n8k16.row.col.f32.f16.f16.f32 "
        "{%0,%1,%2,%3}, {%4,%5,%6,%7}, {%8,%9}, {%0,%1,%2,%3};"
        : "+f"(c[0]), "+f"(c[1]), "+f"(c[2]), "+f"(c[3])
        : "r"(a[0]), "r"(a[1]), "r"(a[2]), "r"(a[3]), "r"(b[0]), "r"(b[1]));
}

__device__ __forceinline__ void ldm_x4(uint32_t* r, const uint32_t* p) {
    uint32_t a = (uint32_t)__cvta_generic_to_shared(p);
    asm volatile("ldmatrix.sync.aligned.m8n8.x4.shared.b16 {%0,%1,%2,%3}, [%4];"
        : "=r"(r[0]), "=r"(r[1]), "=r"(r[2]), "=r"(r[3]) : "r"(a));
}
__device__ __forceinline__ void ldm_x2(uint32_t* r, const uint32_t* p) {
    uint32_t a = (uint32_t)__cvta_generic_to_shared(p);
    asm volatile("ldmatrix.sync.aligned.m8n8.x2.shared.b16 {%0,%1}, [%2];"
        : "=r"(r[0]), "=r"(r[1]) : "r"(a));
}

__device__ __forceinline__ void cpa16(void* smem, const void* g) {
    uint32_t s = (uint32_t)__cvta_generic_to_shared(smem);
    asm volatile("cp.async.cg.shared.global [%0], [%1], 16;" :: "r"(s), "l"(g));
}
__device__ __forceinline__ void cpa_commit() { asm volatile("cp.async.commit_group;"); }
__device__ __forceinline__ void cpa_wait0() { asm volatile("cp.async.wait_group 0;" ::: "memory"); }
__device__ __forceinline__ void cpa_wait1() { asm volatile("cp.async.wait_group 1;" ::: "memory"); }

// ---------------------------------------------------------------------------
// Batched f32 -> f16 conversion
// ---------------------------------------------------------------------------
struct CvtArgs {
    const float* s[7];
    __half* d[7];
    int n4[7];
};

__global__ __launch_bounds__(256) void cvt_f2h(CvtArgs a)
{
    const int z = blockIdx.y;
    const float4* s = (const float4*)a.s[z];
    __half* d = a.d[z];
    const int n4 = a.n4[z];
    for (int i = blockIdx.x * blockDim.x + threadIdx.x; i < n4;
         i += gridDim.x * blockDim.x) {
        float4 f = s[i];
        *(uint2*)(d + (size_t)i * 4) = make_uint2(f2h2(f.x, f.y), f2h2(f.z, f.w));
    }
}

// Bit-pack the mask: bit k of word w = (mask[w*32+k] != 0)
__global__ __launch_bounds__(256) void pack_mask(const int* __restrict__ mask, int n)
{
    const int i = blockIdx.x * 256 + threadIdx.x;
    if (i < n) {
        const uint32_t b = __ballot_sync(0xffffffffu, mask[i] != 0);
        if ((threadIdx.x & 31) == 0) g_pm[i >> 5] = b;
    }
}

// ---------------------------------------------------------------------------
// fp16-input GEMM, 3-stage cp.async pipeline, ONE sync per k-stage.
// MODE 0: f32 row-major. MODE 1: half [b,h,s,dh]. MODE 2: half [b,h,dh,s]
// via smem-transposed coalesced epilogue (reuses pipeline buffers).
// ---------------------------------------------------------------------------
#define HG3_ISSUE(st, k0)                                                          \
    do {                                                                           \
        uint32_t* Ab = sm3 + (st) * 2560;                                          \
        uint32_t* Wb = sm3 + 7680 + (st) * 2560;                                   \
        cpa16(&Ab[sr0 * 20 + sch * 4], abase + (size_t)sr0 * ND + (k0) + sch * 8); \
        cpa16(&Ab[sr1 * 20 + sch * 4], abase + (size_t)sr1 * ND + (k0) + sch * 8); \
        cpa16(&Wb[sr0 * 20 + sch * 4], wbase + (size_t)sr0 * ND + (k0) + sch * 8); \
        cpa16(&Wb[sr1 * 20 + sch * 4], wbase + (size_t)sr1 * ND + (k0) + sch * 8); \
        cpa_commit();                                                              \
    } while (0)

template <int MODE>
__device__ __forceinline__ void hgemm3_body(
    const __half* __restrict__ A, const __half* __restrict__ W,
    const float* __restrict__ bias, void* __restrict__ outv,
    int bm, int bn, uint32_t* sm3)
{
    const int tid = threadIdx.x;
    const int wid = tid >> 5, lane = tid & 31;
    const int g = lane >> 2, t = lane & 3;
    const int wm = (wid & 3) * 32;
    const int wn = (wid >> 2) * 64;

    const int sr0 = tid >> 2, sr1 = sr0 + 64;
    const int sch = tid & 3;

    const int la16 = lane & 15;
    const int lac  = (lane >> 4) * 4;
    const int lb8  = lane & 7;
    const int lbc  = ((lane >> 3) & 1) * 4;

    float c[2][8][4];
#pragma unroll
    for (int i = 0; i < 2; i++)
#pragma unroll
        for (int j = 0; j < 8; j++)
#pragma unroll
            for (int q = 0; q < 4; q++) c[i][j][q] = 0.f;

    const __half* abase = A + (size_t)bm * ND;
    const __half* wbase = W + (size_t)bn * ND;

    HG3_ISSUE(0, 0);
    HG3_ISSUE(1, 32);

    for (int s = 0; s < 32; s++) {
        if (s < 31) cpa_wait1(); else cpa_wait0();
        __syncthreads();
        if (s + 2 < 32) HG3_ISSUE((s + 2) % 3, (s + 2) * 32);

        const uint32_t* Ab = sm3 + (s % 3) * 2560;
        const uint32_t* Wb = sm3 + 7680 + (s % 3) * 2560;
#pragma unroll
        for (int ch = 0; ch < 2; ch++) {
            uint32_t af[2][4];
            ldm_x4(af[0], &Ab[(wm + la16)      * 20 + ch * 8 + lac]);
            ldm_x4(af[1], &Ab[(wm + 16 + la16) * 20 + ch * 8 + lac]);
#pragma unroll
            for (int nt = 0; nt < 8; nt++) {
                uint32_t bf[2];
                ldm_x2(bf, &Wb[(wn + nt * 8 + lb8) * 20 + ch * 8 + lbc]);
                mma_f16(c[0][nt], af[0], bf);
                mma_f16(c[1][nt], af[1], bf);
            }
        }
    }

    if (MODE == 2) {
        // Transposed epilogue through smem: coalesced 16B stores.
        __syncthreads();                       // done reading pipeline buffers
        __half* smT = (__half*)sm3;            // [dh-local 128][m-local 144]
#pragma unroll
        for (int mt = 0; mt < 2; mt++) {
#pragma unroll
            for (int rr = 0; rr < 2; rr++) {
                const int ml = wm + mt * 16 + g + rr * 8;
#pragma unroll
                for (int nt = 0; nt < 8; nt++) {
                    const int dl = wn + nt * 8 + 2 * t;
                    smT[(size_t)dl * 144 + ml] =
                        __float2half_rn(c[mt][nt][rr * 2 + 0] + bias[bn + dl]);
                    smT[(size_t)(dl + 1) * 144 + ml] =
                        __float2half_rn(c[mt][nt][rr * 2 + 1] + bias[bn + dl + 1]);
                }
            }
        }
        __syncthreads();
        // Coalesced writeout: thread -> one dh row, 64 m values (8 x 16B)
        const int dl = tid >> 1;
        const int mh = (tid & 1) * 64;
        const int colg = bn + dl;
        const int h = colg >> 6, dh = colg & 63;
        const int b = bm >> 11;
        const int sBase = (bm & (NS - 1)) + mh;
        __half* o = (__half*)outv + ((size_t)(b * NH + h) * NDH + dh) * NS + sBase;
        const __half* src = smT + (size_t)dl * 144 + mh;
#pragma unroll
        for (int cκ = 0; cκ < 8; cκ++)
            *(uint4*)(o + cκ * 8) = *(const uint4*)(src + cκ * 8);
        return;
    }

#pragma unroll
    for (int mt = 0; mt < 2; mt++) {
#pragma unroll
        for (int rr = 0; rr < 2; rr++) {
            const int m = bm + wm + mt * 16 + g + rr * 8;
            const int b = m >> 11, sIdx = m & (NS - 1);
#pragma unroll
            for (int nt = 0; nt < 8; nt++) {
                const int col = bn + wn + nt * 8 + 2 * t;
                const float vx = c[mt][nt][rr * 2 + 0] + bias[col];
                const float vy = c[mt][nt][rr * 2 + 1] + bias[col + 1];
                if (MODE == 0) {
                    *(float2*)&((float*)outv)[(size_t)m * ND + col] = make_float2(vx, vy);
                } else {
                    const int h = col >> 6, dh = col & 63;
                    *(uint32_t*)&((__half*)outv)[((size_t)(b * NH + h) * NS + sIdx) * NDH + dh] =
                        f2h2(vx, vy);
                }
            }
        }
    }
}

struct P3h {
    const __half* A[3];
    const __half* W[3];
    const float* B[3];
    __half* O[3];
};

__global__ __launch_bounds__(256) void gemm_qkv(P3h p)
{
    extern __shared__ uint32_t sm3[];
    const int z = blockIdx.z;
    if (z != 2)
        hgemm3_body<1>(p.A[z], p.W[z], p.B[z], p.O[z],
                       blockIdx.y * 128, blockIdx.x * 128, sm3);
    else
        hgemm3_body<2>(p.A[z], p.W[z], p.B[z], p.O[z],
                       blockIdx.y * 128, blockIdx.x * 128, sm3);
}

__global__ __launch_bounds__(256) void gemm_out(
    const __half* __restrict__ A, const __half* __restrict__ W,
    const float* __restrict__ bias, float* __restrict__ out)
{
    extern __shared__ uint32_t sm3[];
    hgemm3_body<0>(A, W, bias, out, blockIdx.y * 128, blockIdx.x * 128, sm3);
}

// ---------------------------------------------------------------------------
// Attention v9: 128 q-rows/block, 8 warps x (16 rows x FULL 64 keys).
// v7 MMA structure (independent chains, scalar fragment LDS); K/V staging
// amortized over 8 warps; rowsums warp-local (quad shuffle); E rows are
// warp-private -> __syncwarp instead of a block barrier. 2 BAR/tile.
// smem: Ks 2x64x36, Vs 2x64x36, Es 128x36 = 55,296 B.
// ---------------------------------------------------------------------------
#define NT_TILES (NS / 64)
#define KST 36
__global__ __launch_bounds__(256) void attn_f16(int store_w)
{
    extern __shared__ uint32_t dsm[];
    uint32_t* KsB = dsm;                 // 2 x 2304
    uint32_t* VsB = dsm + 2 * 64 * KST;  // 2 x 2304
    uint32_t* Es  = VsB + 2 * 64 * KST;  // 128 x 36

    const int b = blockIdx.z, h = blockIdx.y;
    const int q0 = blockIdx.x * 128;
    const int tid = threadIdx.x;
    const int wid = tid >> 5, lane = tid & 31;
    const int g = lane >> 2, t = lane & 3;
    const int wm = wid * 16;             // warp's q-row base (0..112)
    const size_t bh = (size_t)(b * NH + h);

    // Q staging: 128 rows x 8 chunks(16B); thread does 4 chunks
    {
        const int qr = tid >> 1;
        const int qc = (tid & 1) * 4;
        const __half* qptr = g_q + (bh * NS + q0) * NDH;
#pragma unroll
        for (int cκ = 0; cκ < 4; cκ++)
            cpa16(&Es[qr * KST + (qc + cκ) * 4], qptr + qr * NDH + (qc + cκ) * 8);
        cpa_commit();
        cpa_wait0();
    }
    __syncthreads();

    uint32_t qf[4][4];
#pragma unroll
    for (int ch = 0; ch < 4; ch++) {
        qf[ch][0] = Es[(wm + g)     * KST + ch * 8 + t];
        qf[ch][1] = Es[(wm + g + 8) * KST + ch * 8 + t];
        qf[ch][2] = Es[(wm + g)     * KST + ch * 8 + t + 4];
        qf[ch][3] = Es[(wm + g + 8) * KST + ch * 8 + t + 4];
    }
    // qf is warp-private (own rows); E writes are also own rows -> no bar.

    float cacc[8][4];
#pragma unroll
    for (int nt = 0; nt < 8; nt++)
#pragma unroll
        for (int q = 0; q < 4; q++) cacc[nt][q] = 0.f;
    float rs0 = 0.f, rs1 = 0.f;

    const uint32_t* pmb = g_pm + (size_t)b * NS * (NS / 32);
    __half* ewbase = g_ew + bh * NS * NS;
    const __half* kbase = g_k + bh * NS * NDH;
    const __half* vbase = g_v + bh * (size_t)NDH * NS;

    const int qr0 = q0 + wm + g, qr1 = qr0 + 8;
    const int er0 = (wm + g) * KST, er1 = (wm + g + 8) * KST;

    // K/V staging coords: 64 rows x 8 chunks each; thread does 2 K + 2 V
    const int sr = tid >> 2;
    const int sch = tid & 3;

    cpa16(&KsB[sr * KST + sch * 4],      kbase + sr * NDH + sch * 8);
    cpa16(&KsB[sr * KST + sch * 4 + 16], kbase + sr * NDH + sch * 8 + 32);
    cpa16(&VsB[sr * KST + sch * 4],      vbase + (size_t)sr * NS + sch * 8);
    cpa16(&VsB[sr * KST + sch * 4 + 16], vbase + (size_t)sr * NS + sch * 8 + 32);
    cpa_commit();

    for (int kt = 0; kt < NT_TILES; kt++) {
        if (kt + 1 < NT_TILES) {
            const int nb = (kt + 1) & 1;
            const __half* kp = kbase + (size_t)(kt + 1) * 64 * NDH;
            const __half* vp = vbase + (size_t)(kt + 1) * 64;
            uint32_t* kd = KsB + nb * 64 * KST;
            uint32_t* vd = VsB + nb * 64 * KST;
            cpa16(&kd[sr * KST + sch * 4],      kp + sr * NDH + sch * 8);
            cpa16(&kd[sr * KST + sch * 4 + 16], kp + sr * NDH + sch * 8 + 32);
            cpa16(&vd[sr * KST + sch * 4],      vp + (size_t)sr * NS + sch * 8);
            cpa16(&vd[sr * KST + sch * 4 + 16], vp + (size_t)sr * NS + sch * 8 + 32);
            cpa_commit();
            cpa_wait1();
        } else {
            cpa_wait0();
        }
        __syncthreads();    // BAR 1: staged tile visible

        const uint32_t* Ks = KsB + (kt & 1) * 64 * KST;
        const uint32_t* Vs = VsB + (kt & 1) * 64 * KST;

        const uint2 mw0 = *(const uint2*)&pmb[(size_t)qr0 * (NS / 32) + kt * 2];
        const uint2 mw1 = *(const uint2*)&pmb[(size_t)qr1 * (NS / 32) + kt * 2];

        // Two key-halves: S (keys half*32..+31) -> exp -> E STS -> PV (ch pair)
#pragma unroll
        for (int hf = 0; hf < 2; hf++) {
            float lg[4][4];
#pragma unroll
            for (int n2 = 0; n2 < 4; n2++)
#pragma unroll
                for (int q = 0; q < 4; q++) lg[n2][q] = 0.f;
#pragma unroll
            for (int ch = 0; ch < 4; ch++) {
#pragma unroll
                for (int n2 = 0; n2 < 4; n2++) {
                    const int kc = hf * 32 + n2 * 8;
                    uint32_t bf[2];
                    bf[0] = Ks[(kc + g) * KST + ch * 8 + t];
                    bf[1] = Ks[(kc + g) * KST + ch * 8 + t + 4];
                    mma_f16(lg[n2], qf[ch], bf);
                }
            }

            const uint32_t w0 = hf ? mw0.y : mw0.x;
            const uint32_t w1 = hf ? mw1.y : mw1.x;
#pragma unroll
            for (int n2 = 0; n2 < 4; n2++) {
                const int klocal = hf * 32 + n2 * 8 + 2 * t;
                const int sh = (klocal & 31);
                float e0 = (w0 >> sh) & 1        ? 0.f : __expf(lg[n2][0] * 0.125f);
                float e1 = (w0 >> (sh + 1)) & 1  ? 0.f : __expf(lg[n2][1] * 0.125f);
                float e2 = (w1 >> sh) & 1        ? 0.f : __expf(lg[n2][2] * 0.125f);
                float e3 = (w1 >> (sh + 1)) & 1  ? 0.f : __expf(lg[n2][3] * 0.125f);
                rs0 += e0 + e1;
                rs1 += e2 + e3;
                const uint32_t p01 = f2h2(e0, e1);
                const uint32_t p23 = f2h2(e2, e3);
                if (store_w) {
                    const int kcg = kt * 64 + klocal;
                    *(uint32_t*)&ewbase[(size_t)qr0 * NS + kcg] = p01;
                    *(uint32_t*)&ewbase[(size_t)qr1 * NS + kcg] = p23;
                }
                const int pair = (klocal >> 1);
                Es[er0 + pair] = p01;
                Es[er1 + pair] = p23;
            }
            __syncwarp();   // own-warp E rows visible to own-warp PV loads

            // PV over this half's keys: ch pair {2hf, 2hf+1}, all 8 dh chunks
#pragma unroll
            for (int cc = 0; cc < 2; cc++) {
                const int ch = hf * 2 + cc;
                uint32_t af[4];
                af[0] = Es[er0 + ch * 8 + t];
                af[1] = Es[er1 + ch * 8 + t];
                af[2] = Es[er0 + ch * 8 + t + 4];
                af[3] = Es[er1 + ch * 8 + t + 4];
#pragma unroll
                for (int nt = 0; nt < 8; nt++) {
                    const int dc = nt * 8 + g;
                    uint32_t bf[2];
                    bf[0] = Vs[dc * KST + ch * 8 + t];
                    bf[1] = Vs[dc * KST + ch * 8 + t + 4];
                    mma_f16(cacc[nt], af, bf);
                }
            }
        }
        __syncthreads();    // BAR 2: K/V reads done before next issue
    }

    // Rowsums: warp-local quad reduce
    rs0 += __shfl_xor_sync(0xffffffffu, rs0, 1);
    rs0 += __shfl_xor_sync(0xffffffffu, rs0, 2);
    rs1 += __shfl_xor_sync(0xffffffffu, rs1, 1);
    rs1 += __shfl_xor_sync(0xffffffffu, rs1, 2);
    if (t == 0) {
        g_rowsum[bh * NS + qr0] = rs0;
        g_rowsum[bh * NS + qr1] = rs1;
    }
    const float inv0 = 1.f / rs0, inv1 = 1.f / rs1;

    // Normalized attn, concat layout, fp16
#pragma unroll
    for (int nt = 0; nt < 8; nt++) {
        const int dh = nt * 8 + 2 * t;
        *(uint32_t*)&g_attn[((size_t)b * NS + qr0) * ND + h * NDH + dh] =
            f2h2(cacc[nt][0] * inv0, cacc[nt][1] * inv0);
        *(uint32_t*)&g_attn[((size_t)b * NS + qr1) * ND + h * NDH + dh] =
            f2h2(cacc[nt][2] * inv1, cacc[nt][3] * inv1);
    }
}

// Normalize: w[row][k] = float(ew_fp16[row][k]) * (1/rowsum[row])
__global__ __launch_bounds__(128) void norm_w(float* __restrict__ w)
{
    const int row = blockIdx.x;
    const float inv = 1.f / g_rowsum[row];
    const uint2* s = (const uint2*)(g_ew + (size_t)row * NS);
    float4* d = (float4*)(w + (size_t)row * NS);
#pragma unroll
    for (int i = threadIdx.x; i < NS / 4; i += 128) {
        uint2 pk = s[i];
        __half2 h0 = *reinterpret_cast<__half2*>(&pk.x);
        __half2 h1 = *reinterpret_cast<__half2*>(&pk.y);
        float2 f0 = __half22float2(h0);
        float2 f1 = __half22float2(h1);
        d[i] = make_float4(f0.x * inv, f0.y * inv, f1.x * inv, f1.y * inv);
    }
}

extern "C" void kernel_launch(void* const* d_in, const int* in_sizes, int n_in,
                              void* d_out, int out_size)
{
    const float* Xq  = (const float*)d_in[0];
    const float* Xk  = (const float*)d_in[1];
    const float* Xv  = (const float*)d_in[2];
    const int*   msk = (const int*)d_in[3];
    const float* Wq  = (const float*)d_in[4];
    const float* bq  = (const float*)d_in[5];
    const float* Wk  = (const float*)d_in[6];
    const float* bk  = (const float*)d_in[7];
    const float* Wv  = (const float*)d_in[8];
    const float* bv  = (const float*)d_in[9];
    const float* Wo  = (const float*)d_in[10];
    const float* bo  = (const float*)d_in[11];

    float* out = (float*)d_out;
    const size_t n_attn = (size_t)NB * NS * ND;
    const size_t n_w    = (size_t)NB * NH * NS * NS;

    float* attn_dst = nullptr;
    float* w_dst = nullptr;
    if ((size_t)out_size >= n_attn + n_w) { attn_dst = out; w_dst = out + n_attn; }
    else if ((size_t)out_size >= n_w)     { w_dst = out; }
    else                                  { attn_dst = out; }

    __half *pxh, *pwh, *pq, *pk, *pv, *pa;
    cudaGetSymbolAddress((void**)&pxh, g_xh);
    cudaGetSymbolAddress((void**)&pwh, g_wh);
    cudaGetSymbolAddress((void**)&pq, g_q);
    cudaGetSymbolAddress((void**)&pk, g_k);
    cudaGetSymbolAddress((void**)&pv, g_v);
    cudaGetSymbolAddress((void**)&pa, g_attn);

    const size_t xN = (size_t)NM * ND;
    const size_t wN = (size_t)ND * ND;

    cudaStream_t s2;
    cudaStreamCreateWithFlags(&s2, cudaStreamNonBlocking);
    cudaEvent_t eA, eB, eC, eD;
    cudaEventCreateWithFlags(&eA, cudaEventDisableTiming);
    cudaEventCreateWithFlags(&eB, cudaEventDisableTiming);
    cudaEventCreateWithFlags(&eC, cudaEventDisableTiming);
    cudaEventCreateWithFlags(&eD, cudaEventDisableTiming);

    // Fork 1: pack_mask overlaps cvt + qkv
    cudaEventRecord(eA, 0);
    cudaStreamWaitEvent(s2, eA, 0);
    {
        const int n = NB * NS * NS;
        pack_mask<<<(n + 255) / 256, 256, 0, s2>>>(msk, n);
    }

    // 1) Convert inputs + weights to fp16
    CvtArgs ca;
    ca.s[0] = Xq; ca.d[0] = pxh + 0 * xN; ca.n4[0] = (int)(xN / 4);
    ca.s[1] = Xk; ca.d[1] = pxh + 1 * xN; ca.n4[1] = (int)(xN / 4);
    ca.s[2] = Xv; ca.d[2] = pxh + 2 * xN; ca.n4[2] = (int)(xN / 4);
    ca.s[3] = Wq; ca.d[3] = pwh + 0 * wN; ca.n4[3] = (int)(wN / 4);
    ca.s[4] = Wk; ca.d[4] = pwh + 1 * wN; ca.n4[4] = (int)(wN / 4);
    ca.s[5] = Wv; ca.d[5] = pwh + 2 * wN; ca.n4[5] = (int)(wN / 4);
    ca.s[6] = Wo; ca.d[6] = pwh + 3 * wN; ca.n4[6] = (int)(wN / 4);
    cvt_f2h<<<dim3(1024, 7), 256>>>(ca);

    // 2) Batched Q/K/V projections (3-stage pipeline)
    const int g3_smem = 15360 * 4;
    cudaFuncSetAttribute(gemm_qkv, cudaFuncAttributeMaxDynamicSharedMemorySize, g3_smem);
    cudaFuncSetAttribute(gemm_out, cudaFuncAttributeMaxDynamicSharedMemorySize, g3_smem);
    P3h p;
    p.A[0] = pxh + 0 * xN; p.W[0] = pwh + 0 * wN; p.B[0] = bq; p.O[0] = pq;
    p.A[1] = pxh + 1 * xN; p.W[1] = pwh + 1 * wN; p.B[1] = bk; p.O[1] = pk;
    p.A[2] = pxh + 2 * xN; p.W[2] = pwh + 2 * wN; p.B[2] = bv; p.O[2] = pv;
    gemm_qkv<<<dim3(ND / 128, NM / 128, 3), 256, g3_smem>>>(p);

    // Join: attn needs packed mask + projections
    cudaEventRecord(eB, s2);
    cudaStreamWaitEvent(0, eB, 0);

    // 3) Attention (128 q-rows per block)
    const int attn_smem = (2 * 64 * KST + 2 * 64 * KST + 128 * KST) * 4;  // 55,296
    cudaFuncSetAttribute(attn_f16, cudaFuncAttributeMaxDynamicSharedMemorySize, attn_smem);
    attn_f16<<<dim3(NS / 128, NH, NB), 256, attn_smem>>>(w_dst ? 1 : 0);

    // 4) norm_w overlapped with output projection
    dim3 ggrid(ND / 128, NM / 128);
    if (w_dst && attn_dst) {
        cudaEventRecord(eC, 0);
        cudaStreamWaitEvent(s2, eC, 0);
        norm_w<<<NB * NH * NS, 128, 0, s2>>>(w_dst);
        gemm_out<<<ggrid, 256, g3_smem>>>(pa, pwh + 3 * wN, bo, attn_dst);
        cudaEventRecord(eD, s2);
        cudaStreamWaitEvent(0, eD, 0);
    } else {
        if (w_dst) norm_w<<<NB * NH * NS, 128>>>(w_dst);
        if (attn_dst) gemm_out<<<ggrid, 256, g3_smem>>>(pa, pwh + 3 * wN, bo, attn_dst);
    }
}